// round 1
// baseline (speedup 1.0000x reference)
#include <cuda_runtime.h>
#include <cuda_bf16.h>

// Problem sizes (fixed by the dataset)
#define N2 320000
#define N1 80000
#define N0 20000
#define TREE 128
#define BASIC 128
#define D 128          // output feature dim of every layer
#define EPSV 1e-5f

// Scratch (alloc-free: __device__ globals)
__device__ float g_agg[N1 * D];      // segment-sum buffer (reused: level0 uses n1*D, level1 uses n0*D)
__device__ float g_h1[N1 * D];       // level-0 node output (h for level 1)

// ---------------------------------------------------------------------------
// zero kernel (agg must be zeroed every replay)
// ---------------------------------------------------------------------------
__global__ void zero_kernel(float* p, int n) {
    int i = blockIdx.x * blockDim.x + threadIdx.x;
    if (i < n) p[i] = 0.0f;
}

// ---------------------------------------------------------------------------
// One fused layer: y[tid] = relu(LN(xs @ W + b))  over 128 output features.
// xs: shared input of length K (K = 128 or 256). Each of the 128 threads
// computes one output feature. Ends with a __syncthreads() so that the
// reduction scratch and xs can be safely reused by the caller.
// ---------------------------------------------------------------------------
__device__ __forceinline__ float layer_ln_relu(
    const float* __restrict__ xs, int K,
    const float* __restrict__ W, const float* __restrict__ b,
    const float* __restrict__ g, const float* __restrict__ be,
    int tid, float* red)
{
    float acc = b[tid];
    // coalesced across threads: W[k*128 + tid]
    const float* wp = W + tid;
    #pragma unroll 8
    for (int k = 0; k < K; ++k) {
        acc = fmaf(xs[k], __ldg(wp + k * D), acc);
    }

    // LayerNorm over the 128 features (one per thread)
    float s = acc, s2 = acc * acc;
    #pragma unroll
    for (int o = 16; o > 0; o >>= 1) {
        s  += __shfl_xor_sync(0xffffffffu, s,  o);
        s2 += __shfl_xor_sync(0xffffffffu, s2, o);
    }
    int w = tid >> 5, l = tid & 31;
    if (l == 0) { red[w] = s; red[4 + w] = s2; }
    __syncthreads();
    s  = red[0] + red[1] + red[2] + red[3];
    s2 = red[4] + red[5] + red[6] + red[7];
    float m   = s  * (1.0f / 128.0f);
    float var = s2 * (1.0f / 128.0f) - m * m;
    float r   = rsqrtf(var + EPSV);
    float y   = (acc - m) * r * g[tid] + be[tid];
    __syncthreads();   // protect red[] + xs[] reuse
    return fmaxf(y, 0.0f);
}

// ---------------------------------------------------------------------------
// Edge kernel: per edge e
//   x  = [h[src[e]], bond[e]]                       (256)
//   y1 = relu(LN(x @ W1 + b1))                      (128)
//   y2 = relu(LN(y1 @ W2 + b2))                     (128)
//   atomicAdd(agg[dst[e]], y2)
// ---------------------------------------------------------------------------
__global__ __launch_bounds__(128)
void edge_kernel(const float* __restrict__ h,
                 const float* __restrict__ bond,
                 const int*   __restrict__ src,
                 const int*   __restrict__ dst,
                 const float* __restrict__ W1, const float* __restrict__ b1,
                 const float* __restrict__ g1, const float* __restrict__ be1,
                 const float* __restrict__ W2, const float* __restrict__ b2,
                 const float* __restrict__ g2, const float* __restrict__ be2,
                 float* __restrict__ agg, int E)
{
    __shared__ float xs[256];
    __shared__ float red[8];
    int e = blockIdx.x;
    if (e >= E) return;
    int tid = threadIdx.x;

    int s = src[e];
    xs[tid]       = h[(long long)s * D + tid];
    xs[128 + tid] = bond[(long long)e * D + tid];
    __syncthreads();

    float y1 = layer_ln_relu(xs, 256, W1, b1, g1, be1, tid, red);
    xs[tid] = y1;
    __syncthreads();
    float y2 = layer_ln_relu(xs, 128, W2, b2, g2, be2, tid, red);

    int dn = dst[e];
    atomicAdd(&agg[(long long)dn * D + tid], y2);
}

// ---------------------------------------------------------------------------
// Node kernel: per node n
//   sx = [ax[n], agg[n]]                            (256)
//   f  = relu(LN(sx @ sW1 + sb1))                   (128)
//   f  = relu(LN(f  @ sW2 + sb2))                   (128)
//   th = [ax[n], f]                                 (256)
//   h  = relu(LN(th @ hW + hb))                     (128)  -> out
// ---------------------------------------------------------------------------
__global__ __launch_bounds__(128)
void node_kernel(const float* __restrict__ ax,
                 const float* __restrict__ agg,
                 const float* __restrict__ sW1, const float* __restrict__ sb1,
                 const float* __restrict__ sg1, const float* __restrict__ sbe1,
                 const float* __restrict__ sW2, const float* __restrict__ sb2,
                 const float* __restrict__ sg2, const float* __restrict__ sbe2,
                 const float* __restrict__ hW,  const float* __restrict__ hb,
                 const float* __restrict__ hg,  const float* __restrict__ hbe,
                 float* __restrict__ out, int N)
{
    __shared__ float xs[256];
    __shared__ float red[8];
    int n = blockIdx.x;
    if (n >= N) return;
    int tid = threadIdx.x;

    float a = ax[(long long)n * D + tid];
    xs[tid]       = a;
    xs[128 + tid] = agg[(long long)n * D + tid];
    __syncthreads();

    float f = layer_ln_relu(xs, 256, sW1, sb1, sg1, sbe1, tid, red);
    xs[tid] = f;
    __syncthreads();
    f = layer_ln_relu(xs, 128, sW2, sb2, sg2, sbe2, tid, red);
    xs[tid]       = a;
    xs[128 + tid] = f;
    __syncthreads();
    float hv = layer_ln_relu(xs, 256, hW, hb, hg, hbe, tid, red);

    out[(long long)n * D + tid] = hv;
}

// ---------------------------------------------------------------------------
// kernel_launch
// Inputs (metadata order):
//  0 subtree_h_top [n2,128]   1 atom_x_1 [n1,128]   2 atom_x_0 [n0,128]
//  3 bond_x_2 [n2,128]        4 bond_x_1 [n1,128]
//  5 branch_W1 [2,256,128]    6 branch_b1 [2,128]   7 branch_g1    8 branch_beta1
//  9 branch_W2 [2,128,128]   10 branch_b2          11 branch_g2   12 branch_beta2
// 13 sub_W1 [2,256,128]      14 sub_b1             15 sub_g1      16 sub_beta1
// 17 sub_W2 [2,128,128]      18 sub_b2             19 sub_g2      20 sub_beta2
// 21 head_W [2,256,128]      22 head_b             23 head_g      24 head_beta
// 25 src_2 [n2] int32        26 dst_2 [n2]         27 src_1 [n1]  28 dst_1 [n1]
// ---------------------------------------------------------------------------
extern "C" void kernel_launch(void* const* d_in, const int* in_sizes, int n_in,
                              void* d_out, int out_size)
{
    const float* subtree_h_top = (const float*)d_in[0];
    const float* atom_x_1      = (const float*)d_in[1];
    const float* atom_x_0      = (const float*)d_in[2];
    const float* bond_x_2      = (const float*)d_in[3];
    const float* bond_x_1      = (const float*)d_in[4];
    const float* branch_W1     = (const float*)d_in[5];
    const float* branch_b1     = (const float*)d_in[6];
    const float* branch_g1     = (const float*)d_in[7];
    const float* branch_beta1  = (const float*)d_in[8];
    const float* branch_W2     = (const float*)d_in[9];
    const float* branch_b2     = (const float*)d_in[10];
    const float* branch_g2     = (const float*)d_in[11];
    const float* branch_beta2  = (const float*)d_in[12];
    const float* sub_W1        = (const float*)d_in[13];
    const float* sub_b1        = (const float*)d_in[14];
    const float* sub_g1        = (const float*)d_in[15];
    const float* sub_beta1     = (const float*)d_in[16];
    const float* sub_W2        = (const float*)d_in[17];
    const float* sub_b2        = (const float*)d_in[18];
    const float* sub_g2        = (const float*)d_in[19];
    const float* sub_beta2     = (const float*)d_in[20];
    const float* head_W        = (const float*)d_in[21];
    const float* head_b        = (const float*)d_in[22];
    const float* head_g        = (const float*)d_in[23];
    const float* head_beta     = (const float*)d_in[24];
    const int*   src_2         = (const int*)d_in[25];
    const int*   dst_2         = (const int*)d_in[26];
    const int*   src_1         = (const int*)d_in[27];
    const int*   dst_1         = (const int*)d_in[28];

    const int n2 = in_sizes[0] / D;
    const int n1 = in_sizes[1] / D;
    const int n0 = in_sizes[2] / D;

    float* agg; cudaGetSymbolAddress((void**)&agg, g_agg);
    float* h1;  cudaGetSymbolAddress((void**)&h1,  g_h1);
    float* out = (float*)d_out;

    const int W1_STRIDE = 256 * D;   // [2,256,128]
    const int W2_STRIDE = 128 * D;   // [2,128,128]
    const int V_STRIDE  = D;         // [2,128]

    // ---------------- level 0 (k=2): E=n2 edges -> n1 nodes ----------------
    {
        int tot = n1 * D;
        zero_kernel<<<(tot + 255) / 256, 256>>>(agg, tot);
        edge_kernel<<<n2, 128>>>(
            subtree_h_top, bond_x_2, src_2, dst_2,
            branch_W1, branch_b1, branch_g1, branch_beta1,
            branch_W2, branch_b2, branch_g2, branch_beta2,
            agg, n2);
        node_kernel<<<n1, 128>>>(
            atom_x_1, agg,
            sub_W1, sub_b1, sub_g1, sub_beta1,
            sub_W2, sub_b2, sub_g2, sub_beta2,
            head_W, head_b, head_g, head_beta,
            h1, n1);
    }

    // ---------------- level 1 (k=1): E=n1 edges -> n0 nodes ----------------
    {
        int tot = n0 * D;
        zero_kernel<<<(tot + 255) / 256, 256>>>(agg, tot);
        edge_kernel<<<n1, 128>>>(
            h1, bond_x_1, src_1, dst_1,
            branch_W1 + W1_STRIDE, branch_b1 + V_STRIDE, branch_g1 + V_STRIDE, branch_beta1 + V_STRIDE,
            branch_W2 + W2_STRIDE, branch_b2 + V_STRIDE, branch_g2 + V_STRIDE, branch_beta2 + V_STRIDE,
            agg, n1);
        node_kernel<<<n0, 128>>>(
            atom_x_0, agg,
            sub_W1 + W1_STRIDE, sub_b1 + V_STRIDE, sub_g1 + V_STRIDE, sub_beta1 + V_STRIDE,
            sub_W2 + W2_STRIDE, sub_b2 + V_STRIDE, sub_g2 + V_STRIDE, sub_beta2 + V_STRIDE,
            head_W + W1_STRIDE, head_b + V_STRIDE, head_g + V_STRIDE, head_beta + V_STRIDE,
            out, n0);
    }
}

// round 2
// speedup vs baseline: 1.8723x; 1.8723x over previous
#include <cuda_runtime.h>
#include <cuda_bf16.h>

#define D 128
#define R 32            // rows (edges/nodes) per block
#define PAD 36          // padded row stride in floats (avoids worst bank conflicts, keeps 16B align)
#define EPSV 1e-5f

// Scratch (alloc-free: __device__ globals)
__device__ float g_agg[80000 * D];
__device__ float g_h1[80000 * D];

// ---------------------------------------------------------------------------
// Packed 2xfp32 helpers (Blackwell FFMA2 — only reachable via PTX f32x2)
// ---------------------------------------------------------------------------
__device__ __forceinline__ unsigned long long ffma2(unsigned long long a,
                                                    unsigned long long b,
                                                    unsigned long long c) {
    unsigned long long d;
    asm("fma.rn.f32x2 %0, %1, %2, %3;" : "=l"(d) : "l"(a), "l"(b), "l"(c));
    return d;
}
__device__ __forceinline__ unsigned long long pack2(float lo, float hi) {
    unsigned long long d;
    asm("mov.b64 %0, {%1, %2};" : "=l"(d) : "f"(lo), "f"(hi));
    return d;
}

union Acc {
    float              f[R];
    unsigned long long u[R / 2];
    float4             v4[R / 4];
};

// ---------------------------------------------------------------------------
// GEMM fragment: acc[r] = sum_k xs[k][r] * W[k*128 + tid] + bias
// xs is [K][PAD] in shared (row-pair values contiguous -> f32x2 lanes).
// Each of the 128 threads owns one output feature for all R rows.
// ---------------------------------------------------------------------------
template <int K>
__device__ __forceinline__ void gemm_col(const float* __restrict__ xs,
                                         const float* __restrict__ W,
                                         float bias, Acc& acc) {
    unsigned long long bb = pack2(bias, bias);
#pragma unroll
    for (int i = 0; i < R / 2; i++) acc.u[i] = bb;

    const float* wp = W + threadIdx.x;
#pragma unroll 2
    for (int k = 0; k < K; k++) {
        float w = __ldg(wp + k * D);
        unsigned long long w2 = pack2(w, w);
        const ulonglong2* xv = (const ulonglong2*)(xs + k * PAD);
#pragma unroll
        for (int q = 0; q < R / 4; q++) {
            ulonglong2 v = xv[q];
            acc.u[2 * q + 0] = ffma2(v.x, w2, acc.u[2 * q + 0]);
            acc.u[2 * q + 1] = ffma2(v.y, w2, acc.u[2 * q + 1]);
        }
    }
}

// Transposed store: xs[tid][0..R-1] = acc (pre- or post-LN activations)
__device__ __forceinline__ void store_rows(float* __restrict__ xs, const Acc& acc) {
    float4* dst = (float4*)(xs + threadIdx.x * PAD);
#pragma unroll
    for (int q = 0; q < R / 4; q++) dst[q] = acc.v4[q];
}

// LN stats over the 128-feature dim for R rows. xs = [128][PAD] pre-activations.
// Warp w handles rows w*8 .. w*8+7.
__device__ __forceinline__ void ln_stats(const float* __restrict__ xs,
                                         float2* __restrict__ stats) {
    int wid = threadIdx.x >> 5, lane = threadIdx.x & 31;
#pragma unroll
    for (int rr = 0; rr < R / 4; rr++) {
        int r = wid * (R / 4) + rr;
        float s = 0.f, s2 = 0.f;
#pragma unroll
        for (int j = 0; j < 4; j++) {
            float p = xs[(lane + 32 * j) * PAD + r];
            s += p;
            s2 = fmaf(p, p, s2);
        }
#pragma unroll
        for (int o = 16; o > 0; o >>= 1) {
            s  += __shfl_xor_sync(0xffffffffu, s,  o);
            s2 += __shfl_xor_sync(0xffffffffu, s2, o);
        }
        if (lane == 0) {
            float m = s * (1.0f / 128.0f);
            float v = s2 * (1.0f / 128.0f) - m * m;
            stats[r] = make_float2(m, rsqrtf(v + EPSV));
        }
    }
}

// Apply LN + ReLU in registers: y = relu((acc-m)*rinv*g + beta)
__device__ __forceinline__ void ln_apply(Acc& acc, const float2* __restrict__ stats,
                                         float gv, float bev) {
#pragma unroll
    for (int r = 0; r < R; r++) {
        float2 st = stats[r];
        float y = fmaf((acc.f[r] - st.x) * st.y, gv, bev);
        acc.f[r] = fmaxf(y, 0.f);
    }
}

#define SMEM_FLOATS (384 * PAD)
#define SMEM_BYTES  (SMEM_FLOATS * 4 + R * 8)

// ---------------------------------------------------------------------------
// Edge kernel: per edge  y2 = relu(LN(relu(LN([h[src],bond] @ W1 + b1)) @ W2 + b2))
//              atomicAdd(agg[dst], y2)
// ---------------------------------------------------------------------------
__global__ __launch_bounds__(128)
void edge_kernel(const float* __restrict__ h,
                 const float* __restrict__ bond,
                 const int* __restrict__ src,
                 const int* __restrict__ dst,
                 const float* __restrict__ W1, const float* __restrict__ b1,
                 const float* __restrict__ g1, const float* __restrict__ be1,
                 const float* __restrict__ W2, const float* __restrict__ b2,
                 const float* __restrict__ g2, const float* __restrict__ be2,
                 float* __restrict__ agg, int E) {
    extern __shared__ float smem[];
    float*  xsA   = smem;                     // [256][PAD]
    float*  xsB   = smem + 256 * PAD;         // [128][PAD]
    float2* stats = (float2*)(smem + SMEM_FLOATS);

    int tid = threadIdx.x;
    long long e0 = (long long)blockIdx.x * R;
    int nvalid = (int)min((long long)R, (long long)E - e0);

    // Gather [h[src], bond] -> xsA (transposed: feature-major rows)
#pragma unroll
    for (int r = 0; r < R; r++) {
        float hv = 0.f, bv = 0.f;
        if (r < nvalid) {
            long long e = e0 + r;
            int s = src[e];
            hv = h[(long long)s * D + tid];
            bv = bond[e * D + tid];
        }
        xsA[tid * PAD + r] = hv;
        xsA[(128 + tid) * PAD + r] = bv;
    }
    __syncthreads();

    Acc acc;
    // Layer 1 (K=256)
    gemm_col<256>(xsA, W1, b1[tid], acc);
    store_rows(xsB, acc);                 // pre-LN
    __syncthreads();
    ln_stats(xsB, stats);
    __syncthreads();
    ln_apply(acc, stats, g1[tid], be1[tid]);
    store_rows(xsB, acc);                 // final y1
    __syncthreads();

    // Layer 2 (K=128)
    gemm_col<128>(xsB, W2, b2[tid], acc);
    __syncthreads();
    store_rows(xsA, acc);                 // pre-LN scratch
    __syncthreads();
    ln_stats(xsA, stats);
    __syncthreads();
    ln_apply(acc, stats, g2[tid], be2[tid]);

    // Scatter-add
    for (int r = 0; r < nvalid; r++) {
        int dn = dst[e0 + r];
        atomicAdd(&agg[(long long)dn * D + tid], acc.f[r]);
    }
}

// ---------------------------------------------------------------------------
// Node kernel: f = relu(LN(relu(LN([ax,agg] @ sW1+sb1)) @ sW2+sb2))
//              out = relu(LN([ax,f] @ hW + hb))
// ---------------------------------------------------------------------------
__global__ __launch_bounds__(128)
void node_kernel(const float* __restrict__ ax,
                 const float* __restrict__ aggin,
                 const float* __restrict__ sW1, const float* __restrict__ sb1,
                 const float* __restrict__ sg1, const float* __restrict__ sbe1,
                 const float* __restrict__ sW2, const float* __restrict__ sb2,
                 const float* __restrict__ sg2, const float* __restrict__ sbe2,
                 const float* __restrict__ hW, const float* __restrict__ hb,
                 const float* __restrict__ hg, const float* __restrict__ hbe,
                 float* __restrict__ out, int N) {
    extern __shared__ float smem[];
    float*  xsA   = smem;                     // [256][PAD]: [0..127]=ax, [128..255]=agg then f
    float*  xsB   = smem + 256 * PAD;         // [128][PAD]
    float2* stats = (float2*)(smem + SMEM_FLOATS);

    int tid = threadIdx.x;
    long long n0 = (long long)blockIdx.x * R;
    int nvalid = (int)min((long long)R, (long long)N - n0);

#pragma unroll
    for (int r = 0; r < R; r++) {
        float av = 0.f, gvv = 0.f;
        if (r < nvalid) {
            long long n = n0 + r;
            av = ax[n * D + tid];
            gvv = aggin[n * D + tid];
        }
        xsA[tid * PAD + r] = av;
        xsA[(128 + tid) * PAD + r] = gvv;
    }
    __syncthreads();

    Acc acc;
    // Layer 1 (K=256): [ax, agg] @ sW1
    gemm_col<256>(xsA, sW1, sb1[tid], acc);
    store_rows(xsB, acc);
    __syncthreads();
    ln_stats(xsB, stats);
    __syncthreads();
    ln_apply(acc, stats, sg1[tid], sbe1[tid]);
    store_rows(xsB, acc);
    __syncthreads();

    // Layer 2 (K=128): f = ... @ sW2
    gemm_col<128>(xsB, sW2, sb2[tid], acc);
    __syncthreads();
    store_rows(xsA + 128 * PAD, acc);     // pre-LN scratch (agg region, done with it)
    __syncthreads();
    ln_stats(xsA + 128 * PAD, stats);
    __syncthreads();
    ln_apply(acc, stats, sg2[tid], sbe2[tid]);
    store_rows(xsA + 128 * PAD, acc);     // final f -> [ax, f] now staged in xsA
    __syncthreads();

    // Layer 3 (K=256): head
    gemm_col<256>(xsA, hW, hb[tid], acc);
    __syncthreads();
    store_rows(xsB, acc);
    __syncthreads();
    ln_stats(xsB, stats);
    __syncthreads();
    ln_apply(acc, stats, hg[tid], hbe[tid]);

    for (int r = 0; r < nvalid; r++) {
        out[(n0 + r) * D + tid] = acc.f[r];
    }
}

// ---------------------------------------------------------------------------
// kernel_launch (input order per metadata, same as round 1)
// ---------------------------------------------------------------------------
extern "C" void kernel_launch(void* const* d_in, const int* in_sizes, int n_in,
                              void* d_out, int out_size) {
    const float* subtree_h_top = (const float*)d_in[0];
    const float* atom_x_1      = (const float*)d_in[1];
    const float* atom_x_0      = (const float*)d_in[2];
    const float* bond_x_2      = (const float*)d_in[3];
    const float* bond_x_1      = (const float*)d_in[4];
    const float* branch_W1     = (const float*)d_in[5];
    const float* branch_b1     = (const float*)d_in[6];
    const float* branch_g1     = (const float*)d_in[7];
    const float* branch_beta1  = (const float*)d_in[8];
    const float* branch_W2     = (const float*)d_in[9];
    const float* branch_b2     = (const float*)d_in[10];
    const float* branch_g2     = (const float*)d_in[11];
    const float* branch_beta2  = (const float*)d_in[12];
    const float* sub_W1        = (const float*)d_in[13];
    const float* sub_b1        = (const float*)d_in[14];
    const float* sub_g1        = (const float*)d_in[15];
    const float* sub_beta1     = (const float*)d_in[16];
    const float* sub_W2        = (const float*)d_in[17];
    const float* sub_b2        = (const float*)d_in[18];
    const float* sub_g2        = (const float*)d_in[19];
    const float* sub_beta2     = (const float*)d_in[20];
    const float* head_W        = (const float*)d_in[21];
    const float* head_b        = (const float*)d_in[22];
    const float* head_g        = (const float*)d_in[23];
    const float* head_beta     = (const float*)d_in[24];
    const int*   src_2         = (const int*)d_in[25];
    const int*   dst_2         = (const int*)d_in[26];
    const int*   src_1         = (const int*)d_in[27];
    const int*   dst_1         = (const int*)d_in[28];

    const int n2 = in_sizes[0] / D;
    const int n1 = in_sizes[1] / D;
    const int n0 = in_sizes[2] / D;

    float* agg; cudaGetSymbolAddress((void**)&agg, g_agg);
    float* h1;  cudaGetSymbolAddress((void**)&h1,  g_h1);
    float* out = (float*)d_out;

    static bool attr_done = false;
    if (!attr_done) {
        cudaFuncSetAttribute(edge_kernel, cudaFuncAttributeMaxDynamicSharedMemorySize, SMEM_BYTES);
        cudaFuncSetAttribute(node_kernel, cudaFuncAttributeMaxDynamicSharedMemorySize, SMEM_BYTES);
        attr_done = true;
    }

    const int W1_STRIDE = 256 * D;
    const int W2_STRIDE = 128 * D;
    const int V_STRIDE  = D;

    // ---------------- level 0 (k=2): n2 edges -> n1 nodes ----------------
    cudaMemsetAsync(agg, 0, (size_t)n1 * D * sizeof(float));
    edge_kernel<<<(n2 + R - 1) / R, 128, SMEM_BYTES>>>(
        subtree_h_top, bond_x_2, src_2, dst_2,
        branch_W1, branch_b1, branch_g1, branch_beta1,
        branch_W2, branch_b2, branch_g2, branch_beta2,
        agg, n2);
    node_kernel<<<(n1 + R - 1) / R, 128, SMEM_BYTES>>>(
        atom_x_1, agg,
        sub_W1, sub_b1, sub_g1, sub_beta1,
        sub_W2, sub_b2, sub_g2, sub_beta2,
        head_W, head_b, head_g, head_beta,
        h1, n1);

    // ---------------- level 1 (k=1): n1 edges -> n0 nodes ----------------
    cudaMemsetAsync(agg, 0, (size_t)n0 * D * sizeof(float));
    edge_kernel<<<(n1 + R - 1) / R, 128, SMEM_BYTES>>>(
        h1, bond_x_1, src_1, dst_1,
        branch_W1 + W1_STRIDE, branch_b1 + V_STRIDE, branch_g1 + V_STRIDE, branch_beta1 + V_STRIDE,
        branch_W2 + W2_STRIDE, branch_b2 + V_STRIDE, branch_g2 + V_STRIDE, branch_beta2 + V_STRIDE,
        agg, n1);
    node_kernel<<<(n0 + R - 1) / R, 128, SMEM_BYTES>>>(
        atom_x_0, agg,
        sub_W1 + W1_STRIDE, sub_b1 + V_STRIDE, sub_g1 + V_STRIDE, sub_beta1 + V_STRIDE,
        sub_W2 + W2_STRIDE, sub_b2 + V_STRIDE, sub_g2 + V_STRIDE, sub_beta2 + V_STRIDE,
        head_W + W1_STRIDE, head_b + V_STRIDE, head_g + V_STRIDE, head_beta + V_STRIDE,
        out, n0);
}